// round 15
// baseline (speedup 1.0000x reference)
#include <cuda_runtime.h>
#include <math.h>

#define NQv 4096
#define WAYv 5
#define Cv 64
#define Tv 25
#define QPB 4                 // queries per group (4096 % 4 == 0)
#define NGRP (NQv/QPB)        // 1024 groups
#define BLK (QPB*WAYv*32)     // 640 threads = 20 warps
#define PADT 1792             // padded per-image tile: 64 x 28

typedef unsigned long long u64;

// ---------------- f32x2 packed helpers ----------------
__device__ __forceinline__ u64 pack2(float lo, float hi){
  u64 r; asm("mov.b64 %0, {%1, %2};" : "=l"(r) : "f"(lo), "f"(hi)); return r;
}
__device__ __forceinline__ void unpack2(u64 v, float& lo, float& hi){
  asm("mov.b64 {%0, %1}, %2;" : "=f"(lo), "=f"(hi) : "l"(v));
}
__device__ __forceinline__ u64 fma2(u64 a, u64 b, u64 c){
  u64 d; asm("fma.rn.f32x2 %0, %1, %2, %3;" : "=l"(d) : "l"(a), "l"(b), "l"(c)); return d;
}
__device__ __forceinline__ u64 mul2(u64 a, u64 b){
  u64 d; asm("mul.rn.f32x2 %0, %1, %2;" : "=l"(d) : "l"(a), "l"(b)); return d;
}
__device__ __forceinline__ float tanh_fast(float a){
  float t; asm("tanh.approx.f32 %0, %1;" : "=f"(t) : "f"(a)); return t;
}
__device__ __forceinline__ float ex2f(float a){
  float t; asm("ex2.approx.f32 %0, %1;" : "=f"(t) : "f"(a)); return t;
}

// ---------------- global scratch (pair-independent precompute, padded) ----------------
__device__ float g_qn[NQv*PADT];     // channel-mean-subtracted qry, 64 x 28 padded
__device__ float g_rq[NQv*Tv];
__device__ float g_tp[NQv*Tv];
__device__ float g_sn[WAYv*PADT];
__device__ float g_rs[WAYv*Tv];
__device__ float g_sp[WAYv*Tv];

// ---------------- shared layout (floats), 16B-aligned vector regions ----------
enum {
  OFF_WQKV = 0,                       // 78 x 28
  OFF_WATT = OFF_WQKV + 78*28,        // 26 x 28
  OFF_WFC1 = OFF_WATT + 26*28,        // 104 x 28
  OFF_WFC2T= OFF_WFC1 + 104*28,       // 104 x 28 (fc2 transposed)
  OFF_WDEC = OFF_WFC2T + 104*28,      // 25 x 28
  OFF_LNGB = OFF_WDEC + 25*28,        // 2 x 56: (g,g,b,b) quads, LN1 then LN2
  OFF_SN   = OFF_LNGB + 112,          // 5 x 1792      (per way)
  OFF_QN   = OFF_SN + 5*PADT,         // QPB x 1792    (per query)
  OFF_SCR  = OFF_QN + QPB*PADT,       // 20 x 25 x 28  (per warp)
  OFF_CORR = OFF_SCR + 20*700,        // 20 x 25 x 29  (per warp)
  OFF_BQKV = OFF_CORR + 20*725,
  OFF_BATT = OFF_BQKV + 78,
  OFF_BFC1 = OFF_BATT + 26,
  OFF_BFC2 = OFF_BFC1 + 104,
  OFF_BDEC = OFF_BFC2 + 26,
  OFF_POS  = OFF_BDEC + 25,           // 25 x 27
  OFF_RS   = OFF_POS + 675,           // 5 x 25
  OFF_SP   = OFF_RS + 125,            // 5 x 25
  OFF_RQ   = OFF_SP + 125,            // QPB x 25
  OFF_TP   = OFF_RQ + QPB*25,         // QPB x 25
  OFF_ATTS = OFF_TP + QPB*25,         // 20 x 32
  OFF_ATTQ = OFF_ATTS + 20*32,        // 20 x 32
  SMEM_FLOATS = OFF_ATTQ + 20*32      // 56840 floats = 227360 B
};

// ---------------- prep: channel-mean sub + l2 + proj, padded output ----------------
__global__ void prep_kernel(const float* __restrict__ in,
                            const float* __restrict__ pw,
                            const float* __restrict__ pb,
                            float* __restrict__ on,
                            float* __restrict__ orr,
                            float* __restrict__ op)
{
  int img = blockIdx.x;
  int t = threadIdx.x;
  if (t >= Tv) return;
  const float* base = in + img*Cv*Tv;
  float v[Cv];
  float s = 0.f;
#pragma unroll
  for (int c = 0; c < Cv; c++){ v[c] = base[c*Tv + t]; s += v[c]; }
  float m = s * (1.f/64.f);
  float ss0=0.f, ss1=0.f, pj0=0.f, pj1=0.f;
#pragma unroll
  for (int c = 0; c < Cv; c += 2){
    float d0 = v[c]-m, d1 = v[c+1]-m;
    on[img*PADT + c*28 + t]     = d0;
    on[img*PADT + (c+1)*28 + t] = d1;
    ss0 += d0*d0; ss1 += d1*d1;
    pj0 += d0*pw[c]; pj1 += d1*pw[c+1];
  }
  orr[img*Tv + t] = rsqrtf(ss0+ss1 + 1e-6f);
  op[img*Tv + t]  = pj0+pj1 + pb[0];
}

// ---------------- packed dot helpers ----------------
__device__ __forceinline__ float dot26p(const float* __restrict__ row, const u64 (&h2)[13]){
  const ulonglong2* r2 = (const ulonglong2*)row;
  u64 a0 = 0ull, a1 = 0ull;
  ulonglong2 v0 = r2[0], v1 = r2[1], v2 = r2[2];
  a0 = fma2(v0.x, h2[0], a0);  a1 = fma2(v0.y, h2[1], a1);
  a0 = fma2(v1.x, h2[2], a0);  a1 = fma2(v1.y, h2[3], a1);
  a0 = fma2(v2.x, h2[4], a0);  a1 = fma2(v2.y, h2[5], a1);
  ulonglong2 v3 = r2[3], v4 = r2[4], v5 = r2[5];
  a0 = fma2(v3.x, h2[6], a0);  a1 = fma2(v3.y, h2[7], a1);
  a0 = fma2(v4.x, h2[8], a0);  a1 = fma2(v4.y, h2[9], a1);
  a0 = fma2(v5.x, h2[10], a0); a1 = fma2(v5.y, h2[11], a1);
  a0 = fma2(((const u64*)row)[12], h2[12], a0);
  float l0,hh0,l1,hh1;
  unpack2(a0,l0,hh0); unpack2(a1,l1,hh1);
  return (l0+hh0)+(l1+hh1);
}

__device__ __forceinline__ float dot13p(const float* __restrict__ row,
                                        const u64 (&qp)[6], float q12){
  const ulonglong2* r2 = (const ulonglong2*)row;
  ulonglong2 v0 = r2[0], v1 = r2[1], v2 = r2[2];
  u64 a0 = 0ull, a1 = 0ull;
  a0 = fma2(v0.x, qp[0], a0); a1 = fma2(v0.y, qp[1], a1);
  a0 = fma2(v1.x, qp[2], a0); a1 = fma2(v1.y, qp[3], a1);
  a0 = fma2(v2.x, qp[4], a0); a1 = fma2(v2.y, qp[5], a1);
  float l0,hh0,l1,hh1;
  unpack2(a0,l0,hh0); unpack2(a1,l1,hh1);
  return (l0+hh0)+(l1+hh1) + q12*row[12];
}

#define M25 0x01FFFFFFu

// ---------------- layernorm -> packed h2, vectorized gamma/beta ----------------
__device__ __forceinline__ void ln_packed(const float (&x)[26], const float* __restrict__ gb,
                                          u64 (&h2)[13])
{
  float s = 0.f;
#pragma unroll
  for (int e = 0; e < 26; e++) s += x[e];
  float m = s * (1.f/26.f);
  float vv = 0.f;
#pragma unroll
  for (int e = 0; e < 26; e++){ float d = x[e]-m; vv += d*d; }
  float r = rsqrtf(vv*(1.f/26.f) + 1e-6f);
  u64 r2 = pack2(r, r);
  const ulonglong2* gb2 = (const ulonglong2*)gb;
#pragma unroll
  for (int e = 0; e < 13; e++){
    ulonglong2 v = gb2[e];
    u64 s2 = pack2(x[2*e]-m, x[2*e+1]-m);
    h2[e] = fma2(mul2(s2, r2), v.x, v.y);
  }
}

// ---------------- pre-LN transformer block, packed activations ----------------
__device__ __forceinline__ void xblock(float (&x)[26], int lane, float* __restrict__ sm,
                                       float* __restrict__ SCR)
{
  u64 h2[13];
  ln_packed(x, sm + OFF_LNGB, h2);

  float ao[26];
#pragma unroll
  for (int head = 0; head < 2; head++){
    float qd[13];
#pragma unroll
    for (int d = 0; d < 13; d++)
      qd[d] = sm[OFF_BQKV + head*13 + d]
            + dot26p(sm + OFF_WQKV + (head*13+d)*28, h2);
    u64 qp[6];
#pragma unroll
    for (int i = 0; i < 6; i++) qp[i] = pack2(qd[2*i], qd[2*i+1]);
    float q12 = qd[12];

#pragma unroll 2
    for (int d = 0; d < 13; d++)
      SCR[lane*28 + d] = sm[OFF_BQKV + 26 + head*13 + d]
                       + dot26p(sm + OFF_WQKV + (26+head*13+d)*28, h2);
    __syncwarp(M25);

    // scores + softmax: 13^-0.5 * log2(e) folded; |score|<<1 so no max-sub;
    // 1/sum folded into AV epilogue.
    float p[25];
    float se = 0.f;
#pragma unroll
    for (int j = 0; j < 25; j++){
      float s = dot13p(SCR + j*28, qp, q12);
      float e2 = ex2f(s * 0.4001316091f);
      p[j] = e2; se += e2;
    }
    float inv = __fdividef(1.f, se);
    __syncwarp(M25);

#pragma unroll 2
    for (int d = 0; d < 13; d++)
      SCR[lane*28 + d] = sm[OFF_BQKV + 52 + head*13 + d]
                       + dot26p(sm + OFF_WQKV + (52+head*13+d)*28, h2);
    __syncwarp(M25);

    u64 oa[6];
#pragma unroll
    for (int i = 0; i < 6; i++) oa[i] = 0ull;
    float o12 = 0.f;
#pragma unroll
    for (int j = 0; j < 25; j++){
      const float* vr = SCR + j*28;
      const ulonglong2* v2 = (const ulonglong2*)vr;
      ulonglong2 a = v2[0], b = v2[1], c = v2[2];
      float pj = p[j];
      u64 pj2 = pack2(pj, pj);
      oa[0] = fma2(a.x, pj2, oa[0]); oa[1] = fma2(a.y, pj2, oa[1]);
      oa[2] = fma2(b.x, pj2, oa[2]); oa[3] = fma2(b.y, pj2, oa[3]);
      oa[4] = fma2(c.x, pj2, oa[4]); oa[5] = fma2(c.y, pj2, oa[5]);
      o12 += pj*vr[12];
    }
    u64 inv2 = pack2(inv, inv);
#pragma unroll
    for (int i = 0; i < 6; i++){
      oa[i] = mul2(oa[i], inv2);
      unpack2(oa[i], ao[head*13 + 2*i], ao[head*13 + 2*i + 1]);
    }
    ao[head*13 + 12] = o12 * inv;
    __syncwarp(M25);
  }

  // attn proj + residual
  {
    u64 ao2[13];
#pragma unroll
    for (int e = 0; e < 13; e++) ao2[e] = pack2(ao[2*e], ao[2*e+1]);
#pragma unroll
    for (int e = 0; e < 26; e++)
      x[e] += sm[OFF_BATT+e] + dot26p(sm + OFF_WATT + e*28, ao2);
  }

  u64 g2ln[13];
  ln_packed(x, sm + OFF_LNGB + 56, g2ln);

  // fused FFN (tanh-GELU)
  {
    u64 xa[13];
#pragma unroll
    for (int e = 0; e < 13; e++)
      xa[e] = pack2(x[2*e] + sm[OFF_BFC2+2*e], x[2*e+1] + sm[OFF_BFC2+2*e+1]);
#pragma unroll 2
    for (int n = 0; n < 104; n++){
      float g = sm[OFF_BFC1+n] + dot26p(sm + OFF_WFC1 + n*28, g2ln);
      float gg = g*g;
      float arg = g * fmaf(gg, 0.0356774081f, 0.7978845608f);
      float th = tanh_fast(arg);
      float hg = 0.5f*g;
      g = fmaf(hg, th, hg);
      u64 g2 = pack2(g, g);
      const float* w2 = sm + OFF_WFC2T + n*28;
      const ulonglong2* w4 = (const ulonglong2*)w2;
      ulonglong2 a = w4[0], b = w4[1], c = w4[2];
      xa[0] = fma2(a.x, g2, xa[0]); xa[1] = fma2(a.y, g2, xa[1]);
      xa[2] = fma2(b.x, g2, xa[2]); xa[3] = fma2(b.y, g2, xa[3]);
      xa[4] = fma2(c.x, g2, xa[4]); xa[5] = fma2(c.y, g2, xa[5]);
      ulonglong2 d4 = w4[3], e4 = w4[4], f4 = w4[5];
      xa[6]  = fma2(d4.x, g2, xa[6]);  xa[7]  = fma2(d4.y, g2, xa[7]);
      xa[8]  = fma2(e4.x, g2, xa[8]);  xa[9]  = fma2(e4.y, g2, xa[9]);
      xa[10] = fma2(f4.x, g2, xa[10]); xa[11] = fma2(f4.y, g2, xa[11]);
      xa[12] = fma2(((const u64*)w2)[12], g2, xa[12]);
    }
#pragma unroll
    for (int e = 0; e < 13; e++) unpack2(xa[e], x[2*e], x[2*e+1]);
  }
}

// ---------------- main fused kernel: persistent CTAs over query groups ------------
__global__ __launch_bounds__(BLK, 1) void pair_kernel(
    const float* __restrict__ pos_x, const float* __restrict__ pos_y,
    const float* __restrict__ ln1_g, const float* __restrict__ ln1_b,
    const float* __restrict__ qkv_w, const float* __restrict__ qkv_b,
    const float* __restrict__ attn_w, const float* __restrict__ attn_b,
    const float* __restrict__ ln2_g, const float* __restrict__ ln2_b,
    const float* __restrict__ fc1_w, const float* __restrict__ fc1_b,
    const float* __restrict__ fc2_w, const float* __restrict__ fc2_b,
    const float* __restrict__ dec_w, const float* __restrict__ dec_b,
    float* __restrict__ out)
{
  extern __shared__ float sm[];
  const int tid = threadIdx.x;

  // ---- one-time staging (weights, SN, POS, biases, RS/SP) ----
  for (int idx = tid; idx < 78*26; idx += BLK)  sm[OFF_WQKV + (idx/26)*28 + idx%26] = qkv_w[idx];
  for (int idx = tid; idx < 26*26; idx += BLK)  sm[OFF_WATT + (idx/26)*28 + idx%26] = attn_w[idx];
  for (int idx = tid; idx < 104*26; idx += BLK) sm[OFF_WFC1 + (idx/26)*28 + idx%26] = fc1_w[idx];
  for (int idx = tid; idx < 26*104; idx += BLK){ int e = idx/104, f = idx%104;
                                                 sm[OFF_WFC2T + f*28 + e] = fc2_w[idx]; }
  for (int idx = tid; idx < 25*26; idx += BLK)  sm[OFF_WDEC + (idx/26)*28 + idx%26] = dec_w[idx];
  if (tid < 52){
    int gi = tid >> 2, r = tid & 3;
    sm[OFF_LNGB + tid]      = (r < 2) ? ln1_g[2*gi + r] : ln1_b[2*gi + r - 2];
    sm[OFF_LNGB + 56 + tid] = (r < 2) ? ln2_g[2*gi + r] : ln2_b[2*gi + r - 2];
  }
  if (tid < 78)  sm[OFF_BQKV+tid] = qkv_b[tid];
  if (tid < 104) sm[OFF_BFC1+tid] = fc1_b[tid];
  if (tid < 26){ sm[OFF_BATT+tid] = attn_b[tid]; sm[OFF_BFC2+tid] = fc2_b[tid]; }
  if (tid >= 32 && tid < 57) sm[OFF_BDEC + tid-32] = dec_b[tid-32];
  for (int idx = tid; idx < 650; idx += BLK){
    int p = idx/26, e = idx%26, px = p/5, py = p%5;
    sm[OFF_POS + p*27 + e] = (e < 13) ? pos_x[py*13 + e] : pos_y[px*13 + (e-13)];
  }
  {
    const float4* src = (const float4*)g_sn;
    float4* dst = (float4*)(sm + OFF_SN);
    for (int idx = tid; idx < 5*PADT/4; idx += BLK) dst[idx] = src[idx];
  }
  for (int idx = tid; idx < 125; idx += BLK){ sm[OFF_RS+idx] = g_rs[idx]; sm[OFF_SP+idx] = g_sp[idx]; }

  const int wid  = tid >> 5;            // 0..19
  const int subq = wid / WAYv;          // query within group
  const int w    = wid - subq*WAYv;     // way
  const int lane = tid & 31;

  float* SNw   = sm + OFF_SN   + w*PADT;
  float* QNq   = sm + OFF_QN   + subq*PADT;
  float* SCR   = sm + OFF_SCR  + wid*700;
  float* CORR  = sm + OFF_CORR + wid*725;
  float* ATTSw = sm + OFF_ATTS + wid*32;
  float* ATTQw = sm + OFF_ATTQ + wid*32;
  const float* RQq = sm + OFF_RQ + subq*25;
  const float* TPq = sm + OFF_TP + subq*25;

  for (int grp = blockIdx.x; grp < NGRP; grp += gridDim.x){
    const int q0 = grp * QPB;
    __syncthreads();   // prior group's QN/RQ/TP reads complete before restage

    // ---- per-group staging: QN (float4 copy of padded tiles), RQ, TP ----
    {
      const float4* src = (const float4*)(g_qn + q0*PADT);
      float4* dst = (float4*)(sm + OFF_QN);
      for (int idx = tid; idx < QPB*PADT/4; idx += BLK) dst[idx] = src[idx];
    }
    for (int idx = tid; idx < QPB*25; idx += BLK){
      int sq = idx/25, j = idx%25;
      sm[OFF_RQ + sq*25 + j] = g_rq[(q0+sq)*25 + j];
      sm[OFF_TP + sq*25 + j] = g_tp[(q0+sq)*25 + j];
    }
    __syncthreads();

    if (lane < 25){
      // ---- corr (packed accumulators) ----
      u64 a2[12];
#pragma unroll
      for (int i = 0; i < 12; i++) a2[i] = 0ull;
      float a24 = 0.f;
      for (int c = 0; c < 64; c++){
        float qc = QNq[c*28 + lane];
        u64 qc2 = pack2(qc, qc);
        const float* srow = SNw + c*28;
        const ulonglong2* s2 = (const ulonglong2*)srow;
        ulonglong2 v0=s2[0], v1=s2[1], v2=s2[2], v3=s2[3], v4=s2[4], v5=s2[5];
        a2[0] = fma2(v0.x,qc2,a2[0]); a2[1] = fma2(v0.y,qc2,a2[1]);
        a2[2] = fma2(v1.x,qc2,a2[2]); a2[3] = fma2(v1.y,qc2,a2[3]);
        a2[4] = fma2(v2.x,qc2,a2[4]); a2[5] = fma2(v2.y,qc2,a2[5]);
        a2[6] = fma2(v3.x,qc2,a2[6]); a2[7] = fma2(v3.y,qc2,a2[7]);
        a2[8] = fma2(v4.x,qc2,a2[8]); a2[9] = fma2(v4.y,qc2,a2[9]);
        a2[10]= fma2(v5.x,qc2,a2[10]);a2[11]= fma2(v5.y,qc2,a2[11]);
        a24 += srow[24]*qc;
      }
      float rq = RQq[lane];
      float acc[25];
#pragma unroll
      for (int i = 0; i < 12; i++) unpack2(a2[i], acc[2*i], acc[2*i+1]);
      acc[24] = a24;
#pragma unroll
      for (int i = 0; i < 25; i++)
        CORR[i*29 + lane] = acc[i] * sm[OFF_RS + w*25 + i] * rq;
      __syncwarp(M25);

      // ---- x1 ----
      float x[26];
#pragma unroll
      for (int e = 0; e < 25; e++) x[e] = CORR[e*29 + lane];
      x[25] = TPq[lane];
#pragma unroll
      for (int e = 0; e < 26; e++) x[e] += sm[OFF_POS + lane*27 + e];

      xblock(x, lane, sm, SCR);

      // dec1 -> SCR
      {
        u64 x2[13];
#pragma unroll
        for (int e = 0; e < 13; e++) x2[e] = pack2(x[2*e], x[2*e+1]);
#pragma unroll 2
        for (int o = 0; o < 25; o++)
          SCR[lane*28 + o] = sm[OFF_BDEC+o] + dot26p(sm + OFF_WDEC + o*28, x2);
      }
      __syncwarp(M25);

      // ---- x2 ----
#pragma unroll
      for (int e = 0; e < 25; e++) x[e] = SCR[e*28 + lane] + CORR[lane*29 + e];
      x[25] = sm[OFF_SP + w*25 + lane];
#pragma unroll
      for (int e = 0; e < 26; e++) x[e] += sm[OFF_POS + lane*27 + e];
      __syncwarp(M25);

      xblock(x, lane, sm, SCR);

      // dec2 + refined row
      float y[25];
      {
        u64 x2[13];
#pragma unroll
        for (int e = 0; e < 13; e++) x2[e] = pack2(x[2*e], x[2*e+1]);
#pragma unroll 2
        for (int o = 0; o < 25; o++)
          y[o] = sm[OFF_BDEC+o] + dot26p(sm + OFF_WDEC + o*28, x2) + CORR[lane*29 + o];
      }
#pragma unroll
      for (int o = 0; o < 25; o++) CORR[lane*29 + o] = y[o];
      __syncwarp(M25);

      // ---- attn_q: row-wise gnorm(ddof=1)/T_attn + softmax (log2e folded) ----
      {
        float s = 0.f;
#pragma unroll
        for (int j = 0; j < 25; j++) s += y[j];
        float m = s*(1.f/25.f);
        float vv = 0.f;
#pragma unroll
        for (int j = 0; j < 25; j++){ float d = y[j]-m; vv += d*d; }
        float inv = 0.2885390082f * rsqrtf(vv*(1.f/24.f) + 1e-5f);  // 0.2*log2(e)
        float se = 0.f;
#pragma unroll
        for (int j = 0; j < 25; j++){ float e2 = ex2f((y[j]-m)*inv); y[j] = e2; se += e2; }
        float is = __fdividef(1.f, se);
#pragma unroll
        for (int j = 0; j < 25; j++) SCR[lane*28 + j] = y[j]*is;
      }
      __syncwarp(M25);
      {
        float s = 0.f;
#pragma unroll
        for (int i = 0; i < 25; i++) s += SCR[i*28 + lane];
        ATTQw[lane] = s;
      }
      __syncwarp(M25);

      // ---- attn_s: column-wise gnorm + softmax ----
      {
        float col[25];
#pragma unroll
        for (int i = 0; i < 25; i++) col[i] = CORR[i*29 + lane];
        float s = 0.f;
#pragma unroll
        for (int i = 0; i < 25; i++) s += col[i];
        float m = s*(1.f/25.f);
        float vv = 0.f;
#pragma unroll
        for (int i = 0; i < 25; i++){ float d = col[i]-m; vv += d*d; }
        float inv = 0.2885390082f * rsqrtf(vv*(1.f/24.f) + 1e-5f);
        float se = 0.f;
#pragma unroll
        for (int i = 0; i < 25; i++){ float e2 = ex2f((col[i]-m)*inv); col[i] = e2; se += e2; }
        float is = __fdividef(1.f, se);
#pragma unroll
        for (int i = 0; i < 25; i++) SCR[i*28 + lane] = col[i]*is;
      }
      __syncwarp(M25);
      {
        float s = 0.f;
#pragma unroll
        for (int j = 0; j < 25; j++) s += SCR[lane*28 + j];
        ATTSw[lane] = s;
      }
    }
    __syncwarp();   // full warp: fences ATTS/ATTQ for lanes 25-31

    // ---- pooling + cosine sim (1/25 scales cancel in the ratio) ----
    {
      int c0 = lane, c1 = lane + 32;
      float sp0=0.f, sp1=0.f, qp0=0.f, qp1=0.f;
#pragma unroll
      for (int t = 0; t < 25; t++){
        float as_ = ATTSw[t], aq_ = ATTQw[t];
        sp0 += as_ * SNw[c0*28 + t];
        sp1 += as_ * SNw[c1*28 + t];
        qp0 += aq_ * QNq[c0*28 + t];
        qp1 += aq_ * QNq[c1*28 + t];
      }
      float dd = sp0*qp0 + sp1*qp1;
      float na = sp0*sp0 + sp1*sp1;
      float nb = qp0*qp0 + qp1*qp1;
#pragma unroll
      for (int off = 16; off; off >>= 1){
        dd += __shfl_xor_sync(0xFFFFFFFFu, dd, off);
        na += __shfl_xor_sync(0xFFFFFFFFu, na, off);
        nb += __shfl_xor_sync(0xFFFFFFFFu, nb, off);
      }
      if (lane == 0){
        float n1 = fmaxf(sqrtf(na)*0.04f, 1e-8f);
        float n2 = fmaxf(sqrtf(nb)*0.04f, 1e-8f);
        out[(q0+subq)*WAYv + w] = (dd*0.0016f) / (n1*n2) * 5.0f;
      }
    }
  }
}

// ---------------- launch ----------------
extern "C" void kernel_launch(void* const* d_in, const int* in_sizes, int n_in,
                              void* d_out, int out_size)
{
  const float* spt    = (const float*)d_in[0];
  const float* qry    = (const float*)d_in[1];
  const float* proj_w = (const float*)d_in[2];
  const float* proj_b = (const float*)d_in[3];
  const float* pos_x  = (const float*)d_in[4];
  const float* pos_y  = (const float*)d_in[5];
  const float* ln1_g  = (const float*)d_in[6];
  const float* ln1_b  = (const float*)d_in[7];
  const float* qkv_w  = (const float*)d_in[8];
  const float* qkv_b  = (const float*)d_in[9];
  const float* attn_w = (const float*)d_in[10];
  const float* attn_b = (const float*)d_in[11];
  const float* ln2_g  = (const float*)d_in[12];
  const float* ln2_b  = (const float*)d_in[13];
  const float* fc1_w  = (const float*)d_in[14];
  const float* fc1_b  = (const float*)d_in[15];
  const float* fc2_w  = (const float*)d_in[16];
  const float* fc2_b  = (const float*)d_in[17];
  const float* dec_w  = (const float*)d_in[18];
  const float* dec_b  = (const float*)d_in[19];
  float* out = (float*)d_out;

  float *qn, *rq, *tp, *sn, *rs, *sp;
  cudaGetSymbolAddress((void**)&qn, g_qn);
  cudaGetSymbolAddress((void**)&rq, g_rq);
  cudaGetSymbolAddress((void**)&tp, g_tp);
  cudaGetSymbolAddress((void**)&sn, g_sn);
  cudaGetSymbolAddress((void**)&rs, g_rs);
  cudaGetSymbolAddress((void**)&sp, g_sp);

  prep_kernel<<<WAYv, 32>>>(spt, proj_w, proj_b, sn, rs, sp);
  prep_kernel<<<NQv, 32>>>(qry, proj_w, proj_b, qn, rq, tp);

  size_t shmem = SMEM_FLOATS * sizeof(float);
  int nsm = 148;
  cudaDeviceGetAttribute(&nsm, cudaDevAttrMultiProcessorCount, 0);
  static int configured = -1;
  if (configured < 0){
    cudaFuncSetAttribute(pair_kernel, cudaFuncAttributeMaxDynamicSharedMemorySize, (int)shmem);
    configured = 1;
  }
  int grid = nsm < NGRP ? nsm : NGRP;
  pair_kernel<<<grid, BLK, shmem>>>(
      pos_x, pos_y, ln1_g, ln1_b, qkv_w, qkv_b, attn_w, attn_b,
      ln2_g, ln2_b, fc1_w, fc1_b, fc2_w, fc2_b, dec_w, dec_b, out);
}

// round 16
// speedup vs baseline: 1.1006x; 1.1006x over previous
#include <cuda_runtime.h>
#include <math.h>

#define NQv 4096
#define WAYv 5
#define Cv 64
#define Tv 25
#define QPB 4                 // queries per CTA (4096 % 4 == 0)
#define BLK (QPB*WAYv*32)     // 640 threads = 20 warps
#define PADT 1792             // padded per-image tile: 64 x 28

typedef unsigned long long u64;

// ---------------- f32x2 packed helpers ----------------
__device__ __forceinline__ u64 pack2(float lo, float hi){
  u64 r; asm("mov.b64 %0, {%1, %2};" : "=l"(r) : "f"(lo), "f"(hi)); return r;
}
__device__ __forceinline__ void unpack2(u64 v, float& lo, float& hi){
  asm("mov.b64 {%0, %1}, %2;" : "=f"(lo), "=f"(hi) : "l"(v));
}
__device__ __forceinline__ u64 fma2(u64 a, u64 b, u64 c){
  u64 d; asm("fma.rn.f32x2 %0, %1, %2, %3;" : "=l"(d) : "l"(a), "l"(b), "l"(c)); return d;
}
__device__ __forceinline__ u64 mul2(u64 a, u64 b){
  u64 d; asm("mul.rn.f32x2 %0, %1, %2;" : "=l"(d) : "l"(a), "l"(b)); return d;
}
__device__ __forceinline__ float tanh_fast(float a){
  float t; asm("tanh.approx.f32 %0, %1;" : "=f"(t) : "f"(a)); return t;
}
__device__ __forceinline__ float ex2f(float a){
  float t; asm("ex2.approx.f32 %0, %1;" : "=f"(t) : "f"(a)); return t;
}

// ---------------- global scratch (pair-independent precompute, padded) ----------------
__device__ float g_qn[NQv*PADT];     // channel-mean-subtracted qry, 64 x 28 padded
__device__ float g_rq[NQv*Tv];
__device__ float g_tp[NQv*Tv];
__device__ float g_sn[WAYv*PADT];
__device__ float g_rs[WAYv*Tv];
__device__ float g_sp[WAYv*Tv];

// ---------------- shared layout (floats), 16B-aligned vector regions ----------
enum {
  OFF_WQKV = 0,                       // 78 x 28
  OFF_WATT = OFF_WQKV + 78*28,        // 26 x 28
  OFF_WFC1 = OFF_WATT + 26*28,        // 104 x 28
  OFF_WFC2T= OFF_WFC1 + 104*28,       // 104 x 28 (fc2 transposed)
  OFF_WDEC = OFF_WFC2T + 104*28,      // 25 x 28
  OFF_LNGB = OFF_WDEC + 25*28,        // 2 x 56: (g,g,b,b) quads, LN1 then LN2
  OFF_SN   = OFF_LNGB + 112,          // 5 x 1792      (per way)
  OFF_QN   = OFF_SN + 5*PADT,         // QPB x 1792    (per query)
  OFF_SCR  = OFF_QN + QPB*PADT,       // 20 x 25 x 28  (per warp)
  OFF_CORR = OFF_SCR + 20*700,        // 20 x 25 x 29  (per warp)
  OFF_BQKV = OFF_CORR + 20*725,
  OFF_BATT = OFF_BQKV + 78,
  OFF_BFC1 = OFF_BATT + 26,
  OFF_BFC2 = OFF_BFC1 + 104,
  OFF_BDEC = OFF_BFC2 + 26,
  OFF_POS  = OFF_BDEC + 25,           // 25 x 27
  OFF_RS   = OFF_POS + 675,           // 5 x 25
  OFF_SP   = OFF_RS + 125,            // 5 x 25
  OFF_RQ   = OFF_SP + 125,            // QPB x 25
  OFF_TP   = OFF_RQ + QPB*25,         // QPB x 25
  OFF_ATTS = OFF_TP + QPB*25,         // 20 x 32
  OFF_ATTQ = OFF_ATTS + 20*32,        // 20 x 32
  SMEM_FLOATS = OFF_ATTQ + 20*32      // 227360 B
};

// ---------------- prep: channel-mean sub + l2 + proj, padded output ----------------
__global__ void prep_kernel(const float* __restrict__ in,
                            const float* __restrict__ pw,
                            const float* __restrict__ pb,
                            float* __restrict__ on,
                            float* __restrict__ orr,
                            float* __restrict__ op)
{
  int img = blockIdx.x;
  int t = threadIdx.x;
  if (t >= Tv) return;
  const float* base = in + img*Cv*Tv;
  float v[Cv];
  float s = 0.f;
#pragma unroll
  for (int c = 0; c < Cv; c++){ v[c] = base[c*Tv + t]; s += v[c]; }
  float m = s * (1.f/64.f);
  float ss0=0.f, ss1=0.f, pj0=0.f, pj1=0.f;
#pragma unroll
  for (int c = 0; c < Cv; c += 2){
    float d0 = v[c]-m, d1 = v[c+1]-m;
    on[img*PADT + c*28 + t]     = d0;
    on[img*PADT + (c+1)*28 + t] = d1;
    ss0 += d0*d0; ss1 += d1*d1;
    pj0 += d0*pw[c]; pj1 += d1*pw[c+1];
  }
  orr[img*Tv + t] = rsqrtf(ss0+ss1 + 1e-6f);
  op[img*Tv + t]  = pj0+pj1 + pb[0];
}

// ---------------- packed dot helpers ----------------
__device__ __forceinline__ float dot26p(const float* __restrict__ row, const u64 (&h2)[13]){
  const ulonglong2* r2 = (const ulonglong2*)row;
  u64 a0 = 0ull, a1 = 0ull;
  ulonglong2 v0 = r2[0], v1 = r2[1], v2 = r2[2];
  a0 = fma2(v0.x, h2[0], a0);  a1 = fma2(v0.y, h2[1], a1);
  a0 = fma2(v1.x, h2[2], a0);  a1 = fma2(v1.y, h2[3], a1);
  a0 = fma2(v2.x, h2[4], a0);  a1 = fma2(v2.y, h2[5], a1);
  ulonglong2 v3 = r2[3], v4 = r2[4], v5 = r2[5];
  a0 = fma2(v3.x, h2[6], a0);  a1 = fma2(v3.y, h2[7], a1);
  a0 = fma2(v4.x, h2[8], a0);  a1 = fma2(v4.y, h2[9], a1);
  a0 = fma2(v5.x, h2[10], a0); a1 = fma2(v5.y, h2[11], a1);
  a0 = fma2(((const u64*)row)[12], h2[12], a0);
  float l0,hh0,l1,hh1;
  unpack2(a0,l0,hh0); unpack2(a1,l1,hh1);
  return (l0+hh0)+(l1+hh1);
}

__device__ __forceinline__ float dot13p(const float* __restrict__ row,
                                        const u64 (&qp)[6], float q12){
  const ulonglong2* r2 = (const ulonglong2*)row;
  ulonglong2 v0 = r2[0], v1 = r2[1], v2 = r2[2];
  u64 a0 = 0ull, a1 = 0ull;
  a0 = fma2(v0.x, qp[0], a0); a1 = fma2(v0.y, qp[1], a1);
  a0 = fma2(v1.x, qp[2], a0); a1 = fma2(v1.y, qp[3], a1);
  a0 = fma2(v2.x, qp[4], a0); a1 = fma2(v2.y, qp[5], a1);
  float l0,hh0,l1,hh1;
  unpack2(a0,l0,hh0); unpack2(a1,l1,hh1);
  return (l0+hh0)+(l1+hh1) + q12*row[12];
}

#define M25 0x01FFFFFFu

// ---------------- layernorm -> packed h2, vectorized gamma/beta ----------------
__device__ __forceinline__ void ln_packed(const float (&x)[26], const float* __restrict__ gb,
                                          u64 (&h2)[13])
{
  float s = 0.f;
#pragma unroll
  for (int e = 0; e < 26; e++) s += x[e];
  float m = s * (1.f/26.f);
  float vv = 0.f;
#pragma unroll
  for (int e = 0; e < 26; e++){ float d = x[e]-m; vv += d*d; }
  float r = rsqrtf(vv*(1.f/26.f) + 1e-6f);
  u64 r2 = pack2(r, r);
  const ulonglong2* gb2 = (const ulonglong2*)gb;
#pragma unroll
  for (int e = 0; e < 13; e++){
    ulonglong2 v = gb2[e];
    u64 s2 = pack2(x[2*e]-m, x[2*e+1]-m);
    h2[e] = fma2(mul2(s2, r2), v.x, v.y);
  }
}

// ---------------- pre-LN transformer block, packed activations ----------------
__device__ __forceinline__ void xblock(float (&x)[26], int lane, float* __restrict__ sm,
                                       float* __restrict__ SCR)
{
  u64 h2[13];
  ln_packed(x, sm + OFF_LNGB, h2);

  float ao[26];
#pragma unroll
  for (int head = 0; head < 2; head++){
    float qd[13];
#pragma unroll
    for (int d = 0; d < 13; d++)
      qd[d] = sm[OFF_BQKV + head*13 + d]
            + dot26p(sm + OFF_WQKV + (head*13+d)*28, h2);
    u64 qp[6];
#pragma unroll
    for (int i = 0; i < 6; i++) qp[i] = pack2(qd[2*i], qd[2*i+1]);
    float q12 = qd[12];

#pragma unroll 2
    for (int d = 0; d < 13; d++)
      SCR[lane*28 + d] = sm[OFF_BQKV + 26 + head*13 + d]
                       + dot26p(sm + OFF_WQKV + (26+head*13+d)*28, h2);
    __syncwarp(M25);

    // scores + softmax: 13^-0.5 * log2(e) folded into one scale; no max-sub
    // (|score|<<1); 1/sum folded into AV epilogue.
    float p[25];
    float se = 0.f;
#pragma unroll
    for (int j = 0; j < 25; j++){
      float s = dot13p(SCR + j*28, qp, q12);
      float e2 = ex2f(s * 0.4001316091f);
      p[j] = e2; se += e2;
    }
    float inv = __fdividef(1.f, se);
    __syncwarp(M25);

#pragma unroll 2
    for (int d = 0; d < 13; d++)
      SCR[lane*28 + d] = sm[OFF_BQKV + 52 + head*13 + d]
                       + dot26p(sm + OFF_WQKV + (52+head*13+d)*28, h2);
    __syncwarp(M25);

    u64 oa[6];
#pragma unroll
    for (int i = 0; i < 6; i++) oa[i] = 0ull;
    float o12 = 0.f;
#pragma unroll
    for (int j = 0; j < 25; j++){
      const float* vr = SCR + j*28;
      const ulonglong2* v2 = (const ulonglong2*)vr;
      ulonglong2 a = v2[0], b = v2[1], c = v2[2];
      float pj = p[j];
      u64 pj2 = pack2(pj, pj);
      oa[0] = fma2(a.x, pj2, oa[0]); oa[1] = fma2(a.y, pj2, oa[1]);
      oa[2] = fma2(b.x, pj2, oa[2]); oa[3] = fma2(b.y, pj2, oa[3]);
      oa[4] = fma2(c.x, pj2, oa[4]); oa[5] = fma2(c.y, pj2, oa[5]);
      o12 += pj*vr[12];
    }
    u64 inv2 = pack2(inv, inv);
#pragma unroll
    for (int i = 0; i < 6; i++){
      oa[i] = mul2(oa[i], inv2);
      unpack2(oa[i], ao[head*13 + 2*i], ao[head*13 + 2*i + 1]);
    }
    ao[head*13 + 12] = o12 * inv;
    __syncwarp(M25);
  }

  // attn proj + residual
  {
    u64 ao2[13];
#pragma unroll
    for (int e = 0; e < 13; e++) ao2[e] = pack2(ao[2*e], ao[2*e+1]);
#pragma unroll
    for (int e = 0; e < 26; e++)
      x[e] += sm[OFF_BATT+e] + dot26p(sm + OFF_WATT + e*28, ao2);
  }

  u64 g2ln[13];
  ln_packed(x, sm + OFF_LNGB + 56, g2ln);

  // fused FFN (tanh-GELU)
  {
    u64 xa[13];
#pragma unroll
    for (int e = 0; e < 13; e++)
      xa[e] = pack2(x[2*e] + sm[OFF_BFC2+2*e], x[2*e+1] + sm[OFF_BFC2+2*e+1]);
#pragma unroll 2
    for (int n = 0; n < 104; n++){
      float g = sm[OFF_BFC1+n] + dot26p(sm + OFF_WFC1 + n*28, g2ln);
      float gg = g*g;
      float arg = g * fmaf(gg, 0.0356774081f, 0.7978845608f);
      float th = tanh_fast(arg);
      float hg = 0.5f*g;
      g = fmaf(hg, th, hg);
      u64 g2 = pack2(g, g);
      const float* w2 = sm + OFF_WFC2T + n*28;
      const ulonglong2* w4 = (const ulonglong2*)w2;
      ulonglong2 a = w4[0], b = w4[1], c = w4[2];
      xa[0] = fma2(a.x, g2, xa[0]); xa[1] = fma2(a.y, g2, xa[1]);
      xa[2] = fma2(b.x, g2, xa[2]); xa[3] = fma2(b.y, g2, xa[3]);
      xa[4] = fma2(c.x, g2, xa[4]); xa[5] = fma2(c.y, g2, xa[5]);
      ulonglong2 d4 = w4[3], e4 = w4[4], f4 = w4[5];
      xa[6]  = fma2(d4.x, g2, xa[6]);  xa[7]  = fma2(d4.y, g2, xa[7]);
      xa[8]  = fma2(e4.x, g2, xa[8]);  xa[9]  = fma2(e4.y, g2, xa[9]);
      xa[10] = fma2(f4.x, g2, xa[10]); xa[11] = fma2(f4.y, g2, xa[11]);
      xa[12] = fma2(((const u64*)w2)[12], g2, xa[12]);
    }
#pragma unroll
    for (int e = 0; e < 13; e++) unpack2(xa[e], x[2*e], x[2*e+1]);
  }
}

// ---------------- main fused kernel: CTA = QPB queries x 5 ways, warp per pair ------
__global__ __launch_bounds__(BLK, 1) void pair_kernel(
    const float* __restrict__ pos_x, const float* __restrict__ pos_y,
    const float* __restrict__ ln1_g, const float* __restrict__ ln1_b,
    const float* __restrict__ qkv_w, const float* __restrict__ qkv_b,
    const float* __restrict__ attn_w, const float* __restrict__ attn_b,
    const float* __restrict__ ln2_g, const float* __restrict__ ln2_b,
    const float* __restrict__ fc1_w, const float* __restrict__ fc1_b,
    const float* __restrict__ fc2_w, const float* __restrict__ fc2_b,
    const float* __restrict__ dec_w, const float* __restrict__ dec_b,
    float* __restrict__ out)
{
  extern __shared__ float sm[];
  const int q0 = blockIdx.x * QPB;
  const int tid = threadIdx.x;

  // ---- stage weights (shared by all 20 warps) ----
  for (int idx = tid; idx < 78*26; idx += BLK)  sm[OFF_WQKV + (idx/26)*28 + idx%26] = qkv_w[idx];
  for (int idx = tid; idx < 26*26; idx += BLK)  sm[OFF_WATT + (idx/26)*28 + idx%26] = attn_w[idx];
  for (int idx = tid; idx < 104*26; idx += BLK) sm[OFF_WFC1 + (idx/26)*28 + idx%26] = fc1_w[idx];
  for (int idx = tid; idx < 26*104; idx += BLK){ int e = idx/104, f = idx%104;
                                                 sm[OFF_WFC2T + f*28 + e] = fc2_w[idx]; }
  for (int idx = tid; idx < 25*26; idx += BLK)  sm[OFF_WDEC + (idx/26)*28 + idx%26] = dec_w[idx];
  if (tid < 52){
    int gi = tid >> 2, r = tid & 3;
    sm[OFF_LNGB + tid]      = (r < 2) ? ln1_g[2*gi + r] : ln1_b[2*gi + r - 2];
    sm[OFF_LNGB + 56 + tid] = (r < 2) ? ln2_g[2*gi + r] : ln2_b[2*gi + r - 2];
  }
  if (tid < 78)  sm[OFF_BQKV+tid] = qkv_b[tid];
  if (tid < 104) sm[OFF_BFC1+tid] = fc1_b[tid];
  if (tid < 26){ sm[OFF_BATT+tid] = attn_b[tid]; sm[OFF_BFC2+tid] = fc2_b[tid]; }
  if (tid >= 32 && tid < 57) sm[OFF_BDEC + tid-32] = dec_b[tid-32];
  for (int idx = tid; idx < 650; idx += BLK){
    int p = idx/26, e = idx%26, px = p/5, py = p%5;
    sm[OFF_POS + p*27 + e] = (e < 13) ? pos_x[py*13 + e] : pos_y[px*13 + (e-13)];
  }
  // padded tiles: straight float4 copies
  {
    const float4* src = (const float4*)g_sn;
    float4* dst = (float4*)(sm + OFF_SN);
    for (int idx = tid; idx < 5*PADT/4; idx += BLK) dst[idx] = src[idx];
  }
  {
    const float4* src = (const float4*)(g_qn + q0*PADT);
    float4* dst = (float4*)(sm + OFF_QN);
    for (int idx = tid; idx < QPB*PADT/4; idx += BLK) dst[idx] = src[idx];
  }
  for (int idx = tid; idx < 125; idx += BLK){ sm[OFF_RS+idx] = g_rs[idx]; sm[OFF_SP+idx] = g_sp[idx]; }
  for (int idx = tid; idx < QPB*25; idx += BLK){
    int sq = idx/25, j = idx%25;
    sm[OFF_RQ + sq*25 + j] = g_rq[(q0+sq)*25 + j];
    sm[OFF_TP + sq*25 + j] = g_tp[(q0+sq)*25 + j];
  }
  __syncthreads();

  const int wid  = tid >> 5;            // 0..19
  const int subq = wid / WAYv;          // query within CTA
  const int w    = wid - subq*WAYv;     // way
  const int lane = tid & 31;
  const int q    = q0 + subq;

  float* SNw   = sm + OFF_SN   + w*PADT;
  float* QNq   = sm + OFF_QN   + subq*PADT;
  float* SCR   = sm + OFF_SCR  + wid*700;
  float* CORR  = sm + OFF_CORR + wid*725;
  float* ATTSw = sm + OFF_ATTS + wid*32;
  float* ATTQw = sm + OFF_ATTQ + wid*32;
  const float* RQq = sm + OFF_RQ + subq*25;
  const float* TPq = sm + OFF_TP + subq*25;

  if (lane < 25){
    // ---- corr (packed accumulators) ----
    u64 a2[12];
#pragma unroll
    for (int i = 0; i < 12; i++) a2[i] = 0ull;
    float a24 = 0.f;
    for (int c = 0; c < 64; c++){
      float qc = QNq[c*28 + lane];
      u64 qc2 = pack2(qc, qc);
      const float* srow = SNw + c*28;
      const ulonglong2* s2 = (const ulonglong2*)srow;
      ulonglong2 v0=s2[0], v1=s2[1], v2=s2[2], v3=s2[3], v4=s2[4], v5=s2[5];
      a2[0] = fma2(v0.x,qc2,a2[0]); a2[1] = fma2(v0.y,qc2,a2[1]);
      a2[2] = fma2(v1.x,qc2,a2[2]); a2[3] = fma2(v1.y,qc2,a2[3]);
      a2[4] = fma2(v2.x,qc2,a2[4]); a2[5] = fma2(v2.y,qc2,a2[5]);
      a2[6] = fma2(v3.x,qc2,a2[6]); a2[7] = fma2(v3.y,qc2,a2[7]);
      a2[8] = fma2(v4.x,qc2,a2[8]); a2[9] = fma2(v4.y,qc2,a2[9]);
      a2[10]= fma2(v5.x,qc2,a2[10]);a2[11]= fma2(v5.y,qc2,a2[11]);
      a24 += srow[24]*qc;
    }
    float rq = RQq[lane];
    float acc[25];
#pragma unroll
    for (int i = 0; i < 12; i++) unpack2(a2[i], acc[2*i], acc[2*i+1]);
    acc[24] = a24;
#pragma unroll
    for (int i = 0; i < 25; i++)
      CORR[i*29 + lane] = acc[i] * sm[OFF_RS + w*25 + i] * rq;
    __syncwarp(M25);

    // ---- x1 ----
    float x[26];
#pragma unroll
    for (int e = 0; e < 25; e++) x[e] = CORR[e*29 + lane];
    x[25] = TPq[lane];
#pragma unroll
    for (int e = 0; e < 26; e++) x[e] += sm[OFF_POS + lane*27 + e];

    xblock(x, lane, sm, SCR);

    // dec1 -> SCR
    {
      u64 x2[13];
#pragma unroll
      for (int e = 0; e < 13; e++) x2[e] = pack2(x[2*e], x[2*e+1]);
#pragma unroll 2
      for (int o = 0; o < 25; o++)
        SCR[lane*28 + o] = sm[OFF_BDEC+o] + dot26p(sm + OFF_WDEC + o*28, x2);
    }
    __syncwarp(M25);

    // ---- x2 ----
#pragma unroll
    for (int e = 0; e < 25; e++) x[e] = SCR[e*28 + lane] + CORR[lane*29 + e];
    x[25] = sm[OFF_SP + w*25 + lane];
#pragma unroll
    for (int e = 0; e < 26; e++) x[e] += sm[OFF_POS + lane*27 + e];
    __syncwarp(M25);

    xblock(x, lane, sm, SCR);

    // dec2 + refined row
    float y[25];
    {
      u64 x2[13];
#pragma unroll
      for (int e = 0; e < 13; e++) x2[e] = pack2(x[2*e], x[2*e+1]);
#pragma unroll 2
      for (int o = 0; o < 25; o++)
        y[o] = sm[OFF_BDEC+o] + dot26p(sm + OFF_WDEC + o*28, x2) + CORR[lane*29 + o];
    }
#pragma unroll
    for (int o = 0; o < 25; o++) CORR[lane*29 + o] = y[o];
    __syncwarp(M25);

    // ---- attn_q: row-wise gnorm(ddof=1)/T_attn + softmax (log2e folded) ----
    {
      float s = 0.f;
#pragma unroll
      for (int j = 0; j < 25; j++) s += y[j];
      float m = s*(1.f/25.f);
      float vv = 0.f;
#pragma unroll
      for (int j = 0; j < 25; j++){ float d = y[j]-m; vv += d*d; }
      float inv = 0.2885390082f * rsqrtf(vv*(1.f/24.f) + 1e-5f);  // 0.2*log2(e)
      float se = 0.f;
#pragma unroll
      for (int j = 0; j < 25; j++){ float e2 = ex2f((y[j]-m)*inv); y[j] = e2; se += e2; }
      float is = __fdividef(1.f, se);
#pragma unroll
      for (int j = 0; j < 25; j++) SCR[lane*28 + j] = y[j]*is;
    }
    __syncwarp(M25);
    {
      float s = 0.f;
#pragma unroll
      for (int i = 0; i < 25; i++) s += SCR[i*28 + lane];
      ATTQw[lane] = s;
    }
    __syncwarp(M25);

    // ---- attn_s: column-wise gnorm + softmax ----
    {
      float col[25];
#pragma unroll
      for (int i = 0; i < 25; i++) col[i] = CORR[i*29 + lane];
      float s = 0.f;
#pragma unroll
      for (int i = 0; i < 25; i++) s += col[i];
      float m = s*(1.f/25.f);
      float vv = 0.f;
#pragma unroll
      for (int i = 0; i < 25; i++){ float d = col[i]-m; vv += d*d; }
      float inv = 0.2885390082f * rsqrtf(vv*(1.f/24.f) + 1e-5f);
      float se = 0.f;
#pragma unroll
      for (int i = 0; i < 25; i++){ float e2 = ex2f((col[i]-m)*inv); col[i] = e2; se += e2; }
      float is = __fdividef(1.f, se);
#pragma unroll
      for (int i = 0; i < 25; i++) SCR[i*28 + lane] = col[i]*is;
    }
    __syncwarp(M25);
    {
      float s = 0.f;
#pragma unroll
      for (int j = 0; j < 25; j++) s += SCR[lane*28 + j];
      ATTSw[lane] = s;
    }
  }
  __syncwarp();   // full warp: fences ATTS/ATTQ for lanes 25-31

  // ---- pooling + cosine sim (1/25 factors cancel; applied once at the end) ----
  {
    int c0 = lane, c1 = lane + 32;
    float sp0=0.f, sp1=0.f, qp0=0.f, qp1=0.f;
#pragma unroll
    for (int t = 0; t < 25; t++){
      float as_ = ATTSw[t], aq_ = ATTQw[t];
      sp0 += as_ * SNw[c0*28 + t];
      sp1 += as_ * SNw[c1*28 + t];
      qp0 += aq_ * QNq[c0*28 + t];
      qp1 += aq_ * QNq[c1*28 + t];
    }
    float dd = sp0*qp0 + sp1*qp1;
    float na = sp0*sp0 + sp1*sp1;
    float nb = qp0*qp0 + qp1*qp1;
#pragma unroll
    for (int off = 16; off; off >>= 1){
      dd += __shfl_xor_sync(0xFFFFFFFFu, dd, off);
      na += __shfl_xor_sync(0xFFFFFFFFu, na, off);
      nb += __shfl_xor_sync(0xFFFFFFFFu, nb, off);
    }
    if (lane == 0){
      float n1 = fmaxf(sqrtf(na)*0.04f, 1e-8f);
      float n2 = fmaxf(sqrtf(nb)*0.04f, 1e-8f);
      out[q*WAYv + w] = (dd*0.0016f) / (n1*n2) * 5.0f;
    }
  }
}

// ---------------- launch ----------------
extern "C" void kernel_launch(void* const* d_in, const int* in_sizes, int n_in,
                              void* d_out, int out_size)
{
  const float* spt    = (const float*)d_in[0];
  const float* qry    = (const float*)d_in[1];
  const float* proj_w = (const float*)d_in[2];
  const float* proj_b = (const float*)d_in[3];
  const float* pos_x  = (const float*)d_in[4];
  const float* pos_y  = (const float*)d_in[5];
  const float* ln1_g  = (const float*)d_in[6];
  const float* ln1_b  = (const float*)d_in[7];
  const float* qkv_w  = (const float*)d_in[8];
  const float* qkv_b  = (const float*)d_in[9];
  const float* attn_w = (const float*)d_in[10];
  const float* attn_b = (const float*)d_in[11];
  const float* ln2_g  = (const float*)d_in[12];
  const float* ln2_b  = (const float*)d_in[13];
  const float* fc1_w  = (const float*)d_in[14];
  const float* fc1_b  = (const float*)d_in[15];
  const float* fc2_w  = (const float*)d_in[16];
  const float* fc2_b  = (const float*)d_in[17];
  const float* dec_w  = (const float*)d_in[18];
  const float* dec_b  = (const float*)d_in[19];
  float* out = (float*)d_out;

  float *qn, *rq, *tp, *sn, *rs, *sp;
  cudaGetSymbolAddress((void**)&qn, g_qn);
  cudaGetSymbolAddress((void**)&rq, g_rq);
  cudaGetSymbolAddress((void**)&tp, g_tp);
  cudaGetSymbolAddress((void**)&sn, g_sn);
  cudaGetSymbolAddress((void**)&rs, g_rs);
  cudaGetSymbolAddress((void**)&sp, g_sp);

  prep_kernel<<<WAYv, 32>>>(spt, proj_w, proj_b, sn, rs, sp);
  prep_kernel<<<NQv, 32>>>(qry, proj_w, proj_b, qn, rq, tp);

  size_t shmem = SMEM_FLOATS * sizeof(float);
  static int configured = -1;
  if (configured < 0){
    cudaFuncSetAttribute(pair_kernel, cudaFuncAttributeMaxDynamicSharedMemorySize, (int)shmem);
    configured = 1;
  }
  pair_kernel<<<NQv/QPB, BLK, shmem>>>(
      pos_x, pos_y, ln1_g, ln1_b, qkv_w, qkv_b, attn_w, attn_b,
      ln2_g, ln2_b, fc1_w, fc1_b, fc2_w, fc2_b, dec_w, dec_b, out);
}

// round 17
// speedup vs baseline: 1.1215x; 1.0190x over previous
#include <cuda_runtime.h>
#include <math.h>

#define NQv 4096
#define WAYv 5
#define Cv 64
#define Tv 25
#define QPB 4                 // queries per CTA (4096 % 4 == 0)
#define BLK (QPB*WAYv*32)     // 640 threads = 20 warps
#define PADT 1792             // padded per-image tile: 64 x 28

typedef unsigned long long u64;

// ---------------- f32x2 packed helpers ----------------
__device__ __forceinline__ u64 pack2(float lo, float hi){
  u64 r; asm("mov.b64 %0, {%1, %2};" : "=l"(r) : "f"(lo), "f"(hi)); return r;
}
__device__ __forceinline__ void unpack2(u64 v, float& lo, float& hi){
  asm("mov.b64 {%0, %1}, %2;" : "=f"(lo), "=f"(hi) : "l"(v));
}
__device__ __forceinline__ u64 fma2(u64 a, u64 b, u64 c){
  u64 d; asm("fma.rn.f32x2 %0, %1, %2, %3;" : "=l"(d) : "l"(a), "l"(b), "l"(c)); return d;
}
__device__ __forceinline__ u64 mul2(u64 a, u64 b){
  u64 d; asm("mul.rn.f32x2 %0, %1, %2;" : "=l"(d) : "l"(a), "l"(b)); return d;
}
__device__ __forceinline__ u64 add2(u64 a, u64 b){
  u64 d; asm("add.rn.f32x2 %0, %1, %2;" : "=l"(d) : "l"(a), "l"(b)); return d;
}
__device__ __forceinline__ float tanh_fast(float a){
  float t; asm("tanh.approx.f32 %0, %1;" : "=f"(t) : "f"(a)); return t;
}
__device__ __forceinline__ float ex2f(float a){
  float t; asm("ex2.approx.f32 %0, %1;" : "=f"(t) : "f"(a)); return t;
}

// ---------------- global scratch (pair-independent precompute, padded) ----------------
__device__ float g_qn[NQv*PADT];     // channel-mean-subtracted qry, 64 x 28 padded
__device__ float g_rq[NQv*Tv];
__device__ float g_tp[NQv*Tv];
__device__ float g_sn[WAYv*PADT];
__device__ float g_rs[WAYv*Tv];
__device__ float g_sp[WAYv*Tv];

// ---------------- shared layout (floats), 16B-aligned vector regions ----------
enum {
  OFF_WQKV = 0,                       // 78 x 28
  OFF_WATT = OFF_WQKV + 78*28,        // 26 x 28
  OFF_WFC1 = OFF_WATT + 26*28,        // 104 x 28
  OFF_WFC2T= OFF_WFC1 + 104*28,       // 104 x 28 (fc2 transposed)
  OFF_WDEC = OFF_WFC2T + 104*28,      // 25 x 28
  OFF_LNGB = OFF_WDEC + 25*28,        // 2 x 56: (g,g,b,b) quads, LN1 then LN2
  OFF_SN   = OFF_LNGB + 112,          // 5 x 1792      (per way)
  OFF_QN   = OFF_SN + 5*PADT,         // QPB x 1792    (per query)
  OFF_SCR  = OFF_QN + QPB*PADT,       // 20 x 25 x 28  (per warp)
  OFF_CORR = OFF_SCR + 20*700,        // 20 x 25 x 29  (per warp)
  OFF_BQKV = OFF_CORR + 20*725,
  OFF_BATT = OFF_BQKV + 78,
  OFF_BFC1 = OFF_BATT + 26,
  OFF_BFC2 = OFF_BFC1 + 104,
  OFF_BDEC = OFF_BFC2 + 26,
  OFF_POS  = OFF_BDEC + 25,           // 25 x 27
  OFF_RS   = OFF_POS + 675,           // 5 x 25
  OFF_SP   = OFF_RS + 125,            // 5 x 25
  OFF_RQ   = OFF_SP + 125,            // QPB x 25
  OFF_TP   = OFF_RQ + QPB*25,         // QPB x 25
  OFF_ATTS = OFF_TP + QPB*25,         // 20 x 32
  OFF_ATTQ = OFF_ATTS + 20*32,        // 20 x 32
  SMEM_FLOATS = OFF_ATTQ + 20*32      // 227360 B
};

// ---------------- prep: channel-mean sub + l2 + proj, padded output ----------------
__global__ void prep_kernel(const float* __restrict__ in,
                            const float* __restrict__ pw,
                            const float* __restrict__ pb,
                            float* __restrict__ on,
                            float* __restrict__ orr,
                            float* __restrict__ op)
{
  int img = blockIdx.x;
  int t = threadIdx.x;
  if (t >= Tv) return;
  const float* base = in + img*Cv*Tv;
  float v[Cv];
  float s = 0.f;
#pragma unroll
  for (int c = 0; c < Cv; c++){ v[c] = base[c*Tv + t]; s += v[c]; }
  float m = s * (1.f/64.f);
  float ss0=0.f, ss1=0.f, pj0=0.f, pj1=0.f;
#pragma unroll
  for (int c = 0; c < Cv; c += 2){
    float d0 = v[c]-m, d1 = v[c+1]-m;
    on[img*PADT + c*28 + t]     = d0;
    on[img*PADT + (c+1)*28 + t] = d1;
    ss0 += d0*d0; ss1 += d1*d1;
    pj0 += d0*pw[c]; pj1 += d1*pw[c+1];
  }
  orr[img*Tv + t] = rsqrtf(ss0+ss1 + 1e-6f);
  op[img*Tv + t]  = pj0+pj1 + pb[0];
}

// ---------------- packed dot helpers (add2 epilogue) ----------------
__device__ __forceinline__ float dot26p(const float* __restrict__ row, const u64 (&h2)[13]){
  const ulonglong2* r2 = (const ulonglong2*)row;
  u64 a0 = 0ull, a1 = 0ull;
  ulonglong2 v0 = r2[0], v1 = r2[1], v2 = r2[2];
  a0 = fma2(v0.x, h2[0], a0);  a1 = fma2(v0.y, h2[1], a1);
  a0 = fma2(v1.x, h2[2], a0);  a1 = fma2(v1.y, h2[3], a1);
  a0 = fma2(v2.x, h2[4], a0);  a1 = fma2(v2.y, h2[5], a1);
  ulonglong2 v3 = r2[3], v4 = r2[4], v5 = r2[5];
  a0 = fma2(v3.x, h2[6], a0);  a1 = fma2(v3.y, h2[7], a1);
  a0 = fma2(v4.x, h2[8], a0);  a1 = fma2(v4.y, h2[9], a1);
  a0 = fma2(v5.x, h2[10], a0); a1 = fma2(v5.y, h2[11], a1);
  a0 = fma2(((const u64*)row)[12], h2[12], a0);
  u64 s = add2(a0, a1);
  float lo, hi; unpack2(s, lo, hi);
  return lo + hi;
}

__device__ __forceinline__ float dot13p(const float* __restrict__ row,
                                        const u64 (&qp)[6], float q12){
  const ulonglong2* r2 = (const ulonglong2*)row;
  ulonglong2 v0 = r2[0], v1 = r2[1], v2 = r2[2];
  u64 a0 = 0ull, a1 = 0ull;
  a0 = fma2(v0.x, qp[0], a0); a1 = fma2(v0.y, qp[1], a1);
  a0 = fma2(v1.x, qp[2], a0); a1 = fma2(v1.y, qp[3], a1);
  a0 = fma2(v2.x, qp[4], a0); a1 = fma2(v2.y, qp[5], a1);
  u64 s = add2(a0, a1);
  float lo, hi; unpack2(s, lo, hi);
  return lo + hi + q12*row[12];
}

#define M25 0x01FFFFFFu

// ---------------- layernorm -> packed h2, vectorized gamma/beta ----------------
__device__ __forceinline__ void ln_packed(const float (&x)[26], const float* __restrict__ gb,
                                          u64 (&h2)[13])
{
  float s = 0.f;
#pragma unroll
  for (int e = 0; e < 26; e++) s += x[e];
  float m = s * (1.f/26.f);
  float vv = 0.f;
#pragma unroll
  for (int e = 0; e < 26; e++){ float d = x[e]-m; vv += d*d; }
  float r = rsqrtf(vv*(1.f/26.f) + 1e-6f);
  u64 r2 = pack2(r, r);
  const ulonglong2* gb2 = (const ulonglong2*)gb;
#pragma unroll
  for (int e = 0; e < 13; e++){
    ulonglong2 v = gb2[e];
    u64 s2 = pack2(x[2*e]-m, x[2*e+1]-m);
    h2[e] = fma2(mul2(s2, r2), v.x, v.y);
  }
}

// ---------------- pre-LN transformer block, packed activations ----------------
// SCR row layout per lane (28 floats): k (pre-scaled) [0..12], pad [13], v [14..26], pad [27]
__device__ __forceinline__ void xblock(float (&x)[26], int lane, float* __restrict__ sm,
                                       float* __restrict__ SCR)
{
  u64 h2[13];
  ln_packed(x, sm + OFF_LNGB, h2);

  float ao[26];
#pragma unroll
  for (int head = 0; head < 2; head++){
    float qd[13];
#pragma unroll
    for (int d = 0; d < 13; d++)
      qd[d] = sm[OFF_BQKV + head*13 + d]
            + dot26p(sm + OFF_WQKV + (head*13+d)*28, h2);
    u64 qp[6];
#pragma unroll
    for (int i = 0; i < 6; i++) qp[i] = pack2(qd[2*i], qd[2*i+1]);
    float q12 = qd[12];

    // merged k (pre-scaled by 13^-0.5*log2e) + v store, one sync
#pragma unroll 2
    for (int d = 0; d < 13; d++){
      SCR[lane*28 + d] = (sm[OFF_BQKV + 26 + head*13 + d]
                        + dot26p(sm + OFF_WQKV + (26+head*13+d)*28, h2)) * 0.4001316091f;
      SCR[lane*28 + 14 + d] = sm[OFF_BQKV + 52 + head*13 + d]
                            + dot26p(sm + OFF_WQKV + (52+head*13+d)*28, h2);
    }
    __syncwarp(M25);

    // scores + softmax (scale folded into k; no max-sub; 1/sum folded into AV)
    float p[25];
    float se = 0.f;
#pragma unroll
    for (int j = 0; j < 25; j++){
      float e2 = ex2f(dot13p(SCR + j*28, qp, q12));
      p[j] = e2; se += e2;
    }
    float inv = __fdividef(1.f, se);

    // AV directly (v already resident, 8B-aligned u64 loads at word offset 14)
    u64 oa[6];
#pragma unroll
    for (int i = 0; i < 6; i++) oa[i] = 0ull;
    float o12 = 0.f;
#pragma unroll
    for (int j = 0; j < 25; j++){
      const u64* vp = (const u64*)(SCR + j*28 + 14);
      u64 w0 = vp[0], w1 = vp[1], w2 = vp[2];
      float pj = p[j];
      u64 pj2 = pack2(pj, pj);
      u64 w3 = vp[3], w4 = vp[4], w5 = vp[5];
      oa[0] = fma2(w0, pj2, oa[0]); oa[1] = fma2(w1, pj2, oa[1]);
      oa[2] = fma2(w2, pj2, oa[2]); oa[3] = fma2(w3, pj2, oa[3]);
      oa[4] = fma2(w4, pj2, oa[4]); oa[5] = fma2(w5, pj2, oa[5]);
      o12 += pj * SCR[j*28 + 26];
    }
    u64 inv2 = pack2(inv, inv);
#pragma unroll
    for (int i = 0; i < 6; i++){
      oa[i] = mul2(oa[i], inv2);
      unpack2(oa[i], ao[head*13 + 2*i], ao[head*13 + 2*i + 1]);
    }
    ao[head*13 + 12] = o12 * inv;
    __syncwarp(M25);   // k/v reads done before SCR is rewritten (next head / dec1)
  }

  // attn proj + residual
  {
    u64 ao2[13];
#pragma unroll
    for (int e = 0; e < 13; e++) ao2[e] = pack2(ao[2*e], ao[2*e+1]);
#pragma unroll
    for (int e = 0; e < 26; e++)
      x[e] += sm[OFF_BATT+e] + dot26p(sm + OFF_WATT + e*28, ao2);
  }

  u64 g2ln[13];
  ln_packed(x, sm + OFF_LNGB + 56, g2ln);

  // fused FFN (tanh-GELU)
  {
    u64 xa[13];
#pragma unroll
    for (int e = 0; e < 13; e++)
      xa[e] = pack2(x[2*e] + sm[OFF_BFC2+2*e], x[2*e+1] + sm[OFF_BFC2+2*e+1]);
#pragma unroll 2
    for (int n = 0; n < 104; n++){
      float g = sm[OFF_BFC1+n] + dot26p(sm + OFF_WFC1 + n*28, g2ln);
      float gg = g*g;
      float arg = g * fmaf(gg, 0.0356774081f, 0.7978845608f);
      float th = tanh_fast(arg);
      float hg = 0.5f*g;
      g = fmaf(hg, th, hg);
      u64 g2 = pack2(g, g);
      const float* w2 = sm + OFF_WFC2T + n*28;
      const ulonglong2* w4 = (const ulonglong2*)w2;
      ulonglong2 a = w4[0], b = w4[1], c = w4[2];
      xa[0] = fma2(a.x, g2, xa[0]); xa[1] = fma2(a.y, g2, xa[1]);
      xa[2] = fma2(b.x, g2, xa[2]); xa[3] = fma2(b.y, g2, xa[3]);
      xa[4] = fma2(c.x, g2, xa[4]); xa[5] = fma2(c.y, g2, xa[5]);
      ulonglong2 d4 = w4[3], e4 = w4[4], f4 = w4[5];
      xa[6]  = fma2(d4.x, g2, xa[6]);  xa[7]  = fma2(d4.y, g2, xa[7]);
      xa[8]  = fma2(e4.x, g2, xa[8]);  xa[9]  = fma2(e4.y, g2, xa[9]);
      xa[10] = fma2(f4.x, g2, xa[10]); xa[11] = fma2(f4.y, g2, xa[11]);
      xa[12] = fma2(((const u64*)w2)[12], g2, xa[12]);
    }
#pragma unroll
    for (int e = 0; e < 13; e++) unpack2(xa[e], x[2*e], x[2*e+1]);
  }
}

// ---------------- main fused kernel: CTA = QPB queries x 5 ways, warp per pair ------
__global__ __launch_bounds__(BLK, 1) void pair_kernel(
    const float* __restrict__ pos_x, const float* __restrict__ pos_y,
    const float* __restrict__ ln1_g, const float* __restrict__ ln1_b,
    const float* __restrict__ qkv_w, const float* __restrict__ qkv_b,
    const float* __restrict__ attn_w, const float* __restrict__ attn_b,
    const float* __restrict__ ln2_g, const float* __restrict__ ln2_b,
    const float* __restrict__ fc1_w, const float* __restrict__ fc1_b,
    const float* __restrict__ fc2_w, const float* __restrict__ fc2_b,
    const float* __restrict__ dec_w, const float* __restrict__ dec_b,
    float* __restrict__ out)
{
  extern __shared__ float sm[];
  const int q0 = blockIdx.x * QPB;
  const int tid = threadIdx.x;

  // ---- stage weights (shared by all 20 warps) ----
  for (int idx = tid; idx < 78*26; idx += BLK)  sm[OFF_WQKV + (idx/26)*28 + idx%26] = qkv_w[idx];
  for (int idx = tid; idx < 26*26; idx += BLK)  sm[OFF_WATT + (idx/26)*28 + idx%26] = attn_w[idx];
  for (int idx = tid; idx < 104*26; idx += BLK) sm[OFF_WFC1 + (idx/26)*28 + idx%26] = fc1_w[idx];
  for (int idx = tid; idx < 26*104; idx += BLK){ int e = idx/104, f = idx%104;
                                                 sm[OFF_WFC2T + f*28 + e] = fc2_w[idx]; }
  for (int idx = tid; idx < 25*26; idx += BLK)  sm[OFF_WDEC + (idx/26)*28 + idx%26] = dec_w[idx];
  if (tid < 52){
    int gi = tid >> 2, r = tid & 3;
    sm[OFF_LNGB + tid]      = (r < 2) ? ln1_g[2*gi + r] : ln1_b[2*gi + r - 2];
    sm[OFF_LNGB + 56 + tid] = (r < 2) ? ln2_g[2*gi + r] : ln2_b[2*gi + r - 2];
  }
  if (tid < 78)  sm[OFF_BQKV+tid] = qkv_b[tid];
  if (tid < 104) sm[OFF_BFC1+tid] = fc1_b[tid];
  if (tid < 26){ sm[OFF_BATT+tid] = attn_b[tid]; sm[OFF_BFC2+tid] = fc2_b[tid]; }
  if (tid >= 32 && tid < 57) sm[OFF_BDEC + tid-32] = dec_b[tid-32];
  for (int idx = tid; idx < 650; idx += BLK){
    int p = idx/26, e = idx%26, px = p/5, py = p%5;
    sm[OFF_POS + p*27 + e] = (e < 13) ? pos_x[py*13 + e] : pos_y[px*13 + (e-13)];
  }
  // padded tiles: straight float4 copies
  {
    const float4* src = (const float4*)g_sn;
    float4* dst = (float4*)(sm + OFF_SN);
    for (int idx = tid; idx < 5*PADT/4; idx += BLK) dst[idx] = src[idx];
  }
  {
    const float4* src = (const float4*)(g_qn + q0*PADT);
    float4* dst = (float4*)(sm + OFF_QN);
    for (int idx = tid; idx < QPB*PADT/4; idx += BLK) dst[idx] = src[idx];
  }
  for (int idx = tid; idx < 125; idx += BLK){ sm[OFF_RS+idx] = g_rs[idx]; sm[OFF_SP+idx] = g_sp[idx]; }
  for (int idx = tid; idx < QPB*25; idx += BLK){
    int sq = idx/25, j = idx%25;
    sm[OFF_RQ + sq*25 + j] = g_rq[(q0+sq)*25 + j];
    sm[OFF_TP + sq*25 + j] = g_tp[(q0+sq)*25 + j];
  }
  __syncthreads();

  const int wid  = tid >> 5;            // 0..19
  const int subq = wid / WAYv;          // query within CTA
  const int w    = wid - subq*WAYv;     // way
  const int lane = tid & 31;
  const int q    = q0 + subq;

  float* SNw   = sm + OFF_SN   + w*PADT;
  float* QNq   = sm + OFF_QN   + subq*PADT;
  float* SCR   = sm + OFF_SCR  + wid*700;
  float* CORR  = sm + OFF_CORR + wid*725;
  float* ATTSw = sm + OFF_ATTS + wid*32;
  float* ATTQw = sm + OFF_ATTQ + wid*32;
  const float* RQq = sm + OFF_RQ + subq*25;
  const float* TPq = sm + OFF_TP + subq*25;

  if (lane < 25){
    // ---- corr (packed accumulators) ----
    u64 a2[12];
#pragma unroll
    for (int i = 0; i < 12; i++) a2[i] = 0ull;
    float a24 = 0.f;
    for (int c = 0; c < 64; c++){
      float qc = QNq[c*28 + lane];
      u64 qc2 = pack2(qc, qc);
      const float* srow = SNw + c*28;
      const ulonglong2* s2 = (const ulonglong2*)srow;
      ulonglong2 v0=s2[0], v1=s2[1], v2=s2[2], v3=s2[3], v4=s2[4], v5=s2[5];
      a2[0] = fma2(v0.x,qc2,a2[0]); a2[1] = fma2(v0.y,qc2,a2[1]);
      a2[2] = fma2(v1.x,qc2,a2[2]); a2[3] = fma2(v1.y,qc2,a2[3]);
      a2[4] = fma2(v2.x,qc2,a2[4]); a2[5] = fma2(v2.y,qc2,a2[5]);
      a2[6] = fma2(v3.x,qc2,a2[6]); a2[7] = fma2(v3.y,qc2,a2[7]);
      a2[8] = fma2(v4.x,qc2,a2[8]); a2[9] = fma2(v4.y,qc2,a2[9]);
      a2[10]= fma2(v5.x,qc2,a2[10]);a2[11]= fma2(v5.y,qc2,a2[11]);
      a24 += srow[24]*qc;
    }
    float rq = RQq[lane];
    float acc[25];
#pragma unroll
    for (int i = 0; i < 12; i++) unpack2(a2[i], acc[2*i], acc[2*i+1]);
    acc[24] = a24;
#pragma unroll
    for (int i = 0; i < 25; i++)
      CORR[i*29 + lane] = acc[i] * sm[OFF_RS + w*25 + i] * rq;
    __syncwarp(M25);

    // ---- x1 ----
    float x[26];
#pragma unroll
    for (int e = 0; e < 25; e++) x[e] = CORR[e*29 + lane];
    x[25] = TPq[lane];
#pragma unroll
    for (int e = 0; e < 26; e++) x[e] += sm[OFF_POS + lane*27 + e];

    xblock(x, lane, sm, SCR);

    // dec1 -> SCR
    {
      u64 x2[13];
#pragma unroll
      for (int e = 0; e < 13; e++) x2[e] = pack2(x[2*e], x[2*e+1]);
#pragma unroll 2
      for (int o = 0; o < 25; o++)
        SCR[lane*28 + o] = sm[OFF_BDEC+o] + dot26p(sm + OFF_WDEC + o*28, x2);
    }
    __syncwarp(M25);

    // ---- x2 ----
#pragma unroll
    for (int e = 0; e < 25; e++) x[e] = SCR[e*28 + lane] + CORR[lane*29 + e];
    x[25] = sm[OFF_SP + w*25 + lane];
#pragma unroll
    for (int e = 0; e < 26; e++) x[e] += sm[OFF_POS + lane*27 + e];
    __syncwarp(M25);

    xblock(x, lane, sm, SCR);

    // dec2 + refined row
    float y[25];
    {
      u64 x2[13];
#pragma unroll
      for (int e = 0; e < 13; e++) x2[e] = pack2(x[2*e], x[2*e+1]);
#pragma unroll 2
      for (int o = 0; o < 25; o++)
        y[o] = sm[OFF_BDEC+o] + dot26p(sm + OFF_WDEC + o*28, x2) + CORR[lane*29 + o];
    }
#pragma unroll
    for (int o = 0; o < 25; o++) CORR[lane*29 + o] = y[o];
    __syncwarp(M25);

    // ---- attn_q: row-wise gnorm(ddof=1)/T_attn + softmax (log2e folded) ----
    {
      float s = 0.f;
#pragma unroll
      for (int j = 0; j < 25; j++) s += y[j];
      float m = s*(1.f/25.f);
      float vv = 0.f;
#pragma unroll
      for (int j = 0; j < 25; j++){ float d = y[j]-m; vv += d*d; }
      float inv = 0.2885390082f * rsqrtf(vv*(1.f/24.f) + 1e-5f);  // 0.2*log2(e)
      float se = 0.f;
#pragma unroll
      for (int j = 0; j < 25; j++){ float e2 = ex2f((y[j]-m)*inv); y[j] = e2; se += e2; }
      float is = __fdividef(1.f, se);
#pragma unroll
      for (int j = 0; j < 25; j++) SCR[lane*28 + j] = y[j]*is;
    }
    __syncwarp(M25);
    {
      float s = 0.f;
#pragma unroll
      for (int i = 0; i < 25; i++) s += SCR[i*28 + lane];
      ATTQw[lane] = s;
    }
    __syncwarp(M25);

    // ---- attn_s: column-wise gnorm + softmax ----
    {
      float col[25];
#pragma unroll
      for (int i = 0; i < 25; i++) col[i] = CORR[i*29 + lane];
      float s = 0.f;
#pragma unroll
      for (int i = 0; i < 25; i++) s += col[i];
      float m = s*(1.f/25.f);
      float vv = 0.f;
#pragma unroll
      for (int i = 0; i < 25; i++){ float d = col[i]-m; vv += d*d; }
      float inv = 0.2885390082f * rsqrtf(vv*(1.f/24.f) + 1e-5f);
      float se = 0.f;
#pragma unroll
      for (int i = 0; i < 25; i++){ float e2 = ex2f((col[i]-m)*inv); col[i] = e2; se += e2; }
      float is = __fdividef(1.f, se);
#pragma unroll
      for (int i = 0; i < 25; i++) SCR[i*28 + lane] = col[i]*is;
    }
    __syncwarp(M25);
    {
      float s = 0.f;
#pragma unroll
      for (int j = 0; j < 25; j++) s += SCR[lane*28 + j];
      ATTSw[lane] = s;
    }
  }
  __syncwarp();   // full warp: fences ATTS/ATTQ for lanes 25-31

  // ---- pooling + cosine sim (1/25 factors cancel; applied once at the end) ----
  {
    int c0 = lane, c1 = lane + 32;
    float sp0=0.f, sp1=0.f, qp0=0.f, qp1=0.f;
#pragma unroll
    for (int t = 0; t < 25; t++){
      float as_ = ATTSw[t], aq_ = ATTQw[t];
      sp0 += as_ * SNw[c0*28 + t];
      sp1 += as_ * SNw[c1*28 + t];
      qp0 += aq_ * QNq[c0*28 + t];
      qp1 += aq_ * QNq[c1*28 + t];
    }
    float dd = sp0*qp0 + sp1*qp1;
    float na = sp0*sp0 + sp1*sp1;
    float nb = qp0*qp0 + qp1*qp1;
#pragma unroll
    for (int off = 16; off; off >>= 1){
      dd += __shfl_xor_sync(0xFFFFFFFFu, dd, off);
      na += __shfl_xor_sync(0xFFFFFFFFu, na, off);
      nb += __shfl_xor_sync(0xFFFFFFFFu, nb, off);
    }
    if (lane == 0){
      float n1 = fmaxf(sqrtf(na)*0.04f, 1e-8f);
      float n2 = fmaxf(sqrtf(nb)*0.04f, 1e-8f);
      out[q*WAYv + w] = (dd*0.0016f) / (n1*n2) * 5.0f;
    }
  }
}

// ---------------- launch ----------------
extern "C" void kernel_launch(void* const* d_in, const int* in_sizes, int n_in,
                              void* d_out, int out_size)
{
  const float* spt    = (const float*)d_in[0];
  const float* qry    = (const float*)d_in[1];
  const float* proj_w = (const float*)d_in[2];
  const float* proj_b = (const float*)d_in[3];
  const float* pos_x  = (const float*)d_in[4];
  const float* pos_y  = (const float*)d_in[5];
  const float* ln1_g  = (const float*)d_in[6];
  const float* ln1_b  = (const float*)d_in[7];
  const float* qkv_w  = (const float*)d_in[8];
  const float* qkv_b  = (const float*)d_in[9];
  const float* attn_w = (const float*)d_in[10];
  const float* attn_b = (const float*)d_in[11];
  const float* ln2_g  = (const float*)d_in[12];
  const float* ln2_b  = (const float*)d_in[13];
  const float* fc1_w  = (const float*)d_in[14];
  const float* fc1_b  = (const float*)d_in[15];
  const float* fc2_w  = (const float*)d_in[16];
  const float* fc2_b  = (const float*)d_in[17];
  const float* dec_w  = (const float*)d_in[18];
  const float* dec_b  = (const float*)d_in[19];
  float* out = (float*)d_out;

  float *qn, *rq, *tp, *sn, *rs, *sp;
  cudaGetSymbolAddress((void**)&qn, g_qn);
  cudaGetSymbolAddress((void**)&rq, g_rq);
  cudaGetSymbolAddress((void**)&tp, g_tp);
  cudaGetSymbolAddress((void**)&sn, g_sn);
  cudaGetSymbolAddress((void**)&rs, g_rs);
  cudaGetSymbolAddress((void**)&sp, g_sp);

  prep_kernel<<<WAYv, 32>>>(spt, proj_w, proj_b, sn, rs, sp);
  prep_kernel<<<NQv, 32>>>(qry, proj_w, proj_b, qn, rq, tp);

  size_t shmem = SMEM_FLOATS * sizeof(float);
  static int configured = -1;
  if (configured < 0){
    cudaFuncSetAttribute(pair_kernel, cudaFuncAttributeMaxDynamicSharedMemorySize, (int)shmem);
    configured = 1;
  }
  pair_kernel<<<NQv/QPB, BLK, shmem>>>(
      pos_x, pos_y, ln1_g, ln1_b, qkv_w, qkv_b, attn_w, attn_b,
      ln2_g, ln2_b, fc1_w, fc1_b, fc2_w, fc2_b, dec_w, dec_b, out);
}